// round 7
// baseline (speedup 1.0000x reference)
#include <cuda_runtime.h>
#include <cuda_bf16.h>
#include <math.h>
#include <stdint.h>

#define N_TOK 4096
#define DIM   1024
#define FDIM  4096
#define NEXP  8

// ---------------------------------------------------------------------------
// Scratch (static device globals; no runtime allocation)
__device__ __nv_bfloat16 g_x_hi[(size_t)N_TOK * DIM];
__device__ __nv_bfloat16 g_x_lo[(size_t)N_TOK * DIM];
__device__ __nv_bfloat16 g_w1t_hi[(size_t)NEXP * FDIM * DIM];   // [e][f][d]
__device__ __nv_bfloat16 g_w1t_lo[(size_t)NEXP * FDIM * DIM];
__device__ __nv_bfloat16 g_w2t_hi[(size_t)NEXP * DIM * FDIM];   // [e][d][f]
__device__ __nv_bfloat16 g_w2t_lo[(size_t)NEXP * DIM * FDIM];
__device__ __nv_bfloat16 g_h_hi[(size_t)2 * N_TOK * FDIM];      // [slot*N_TOK+tok][f]
__device__ __nv_bfloat16 g_h_lo[(size_t)2 * N_TOK * FDIM];
__device__ int   g_list[NEXP * N_TOK];
__device__ float g_listp[NEXP * N_TOK];
__device__ int   g_cnt[NEXP];
__device__ float g_tpe[NEXP];
__device__ float g_psum[NEXP];

// ---------------------------------------------------------------------------
// PTX helpers (sm_80-era only: cp.async, ldmatrix, mma.sync — valid on sm_100)
static __device__ __forceinline__ uint32_t smem_u32(const void* p) {
    uint32_t a;
    asm("{ .reg .u64 t; cvta.to.shared.u64 t, %1; cvt.u32.u64 %0, t; }" : "=r"(a) : "l"(p));
    return a;
}
static __device__ __forceinline__ void cp16(uint32_t dst, const void* src) {
    asm volatile("cp.async.cg.shared.global [%0], [%1], 16;" :: "r"(dst), "l"(src));
}
#define CP_COMMIT()  asm volatile("cp.async.commit_group;" ::: "memory")
#define CP_WAIT1()   asm volatile("cp.async.wait_group 1;" ::: "memory")
#define CP_WAIT0()   asm volatile("cp.async.wait_group 0;" ::: "memory")

static __device__ __forceinline__ void ldsm4(uint32_t& r0, uint32_t& r1, uint32_t& r2,
                                             uint32_t& r3, uint32_t addr) {
    asm volatile("ldmatrix.sync.aligned.m8n8.x4.shared.b16 {%0,%1,%2,%3}, [%4];"
                 : "=r"(r0), "=r"(r1), "=r"(r2), "=r"(r3) : "r"(addr));
}
static __device__ __forceinline__ void mma16816(float* c, const uint32_t* a, const uint32_t* b) {
    asm volatile(
        "mma.sync.aligned.m16n8k16.row.col.f32.bf16.bf16.f32 "
        "{%0,%1,%2,%3}, {%4,%5,%6,%7}, {%8,%9}, {%0,%1,%2,%3};"
        : "+f"(c[0]), "+f"(c[1]), "+f"(c[2]), "+f"(c[3])
        : "r"(a[0]), "r"(a[1]), "r"(a[2]), "r"(a[3]), "r"(b[0]), "r"(b[1]));
}

// ---------------------------------------------------------------------------
__global__ void zero_kernel(float* __restrict__ out, int out_size) {
    int i = blockIdx.x * blockDim.x + threadIdx.x;
    if (i < out_size) out[i] = 0.0f;
    if (blockIdx.x == 0 && threadIdx.x < NEXP) {
        g_cnt[threadIdx.x]  = 0;
        g_tpe[threadIdx.x]  = 0.0f;
        g_psum[threadIdx.x] = 0.0f;
    }
}

// ---------------------------------------------------------------------------
__global__ __launch_bounds__(128) void gate_kernel(const float* __restrict__ x,
                                                   const float* __restrict__ gw) {
    const int n = blockIdx.x;
    const int t = threadIdx.x;
    float acc[NEXP];
#pragma unroll
    for (int e = 0; e < NEXP; e++) acc[e] = 0.0f;

    const float* xr = x + (size_t)n * DIM;
    for (int i = t; i < DIM; i += 128) {
        float xv = xr[i];
        const float* g = gw + (size_t)i * NEXP;
#pragma unroll
        for (int e = 0; e < NEXP; e++) acc[e] += xv * g[e];
    }

    __shared__ float red[128];
    __shared__ float logits[NEXP];
    for (int e = 0; e < NEXP; e++) {
        red[t] = acc[e];
        __syncthreads();
        for (int s = 64; s > 0; s >>= 1) {
            if (t < s) red[t] += red[t + s];
            __syncthreads();
        }
        if (t == 0) logits[e] = red[0];
        __syncthreads();
    }

    if (t == 0) {
        float mx = logits[0];
#pragma unroll
        for (int e = 1; e < NEXP; e++) mx = fmaxf(mx, logits[e]);
        float p[NEXP];
        float s = 0.0f;
#pragma unroll
        for (int e = 0; e < NEXP; e++) { p[e] = expf(logits[e] - mx); s += p[e]; }
        float inv = 1.0f / s;
#pragma unroll
        for (int e = 0; e < NEXP; e++) {
            p[e] *= inv;
            atomicAdd(&g_psum[e], p[e]);
        }
        int i0 = 0;
#pragma unroll
        for (int e = 1; e < NEXP; e++) if (p[e] > p[i0]) i0 = e;
        int i1 = (i0 == 0) ? 1 : 0;
#pragma unroll
        for (int e = 0; e < NEXP; e++) {
            if (e == i0) continue;
            if (p[e] > p[i1]) i1 = e;
        }
        float ssum = p[i0] + p[i1];
        float pn0 = p[i0] / (ssum + 1e-8f);
        float pn1 = p[i1] / (ssum + 1e-8f);
        atomicAdd(&g_tpe[i0], pn0);
        atomicAdd(&g_tpe[i1], pn1);
        int pos0 = atomicAdd(&g_cnt[i0], 1);
        g_list[i0 * N_TOK + pos0]  = n * 2 + 0;
        g_listp[i0 * N_TOK + pos0] = pn0;
        int pos1 = atomicAdd(&g_cnt[i1], 1);
        g_list[i1 * N_TOK + pos1]  = n * 2 + 1;
        g_listp[i1 * N_TOK + pos1] = pn1;
    }
}

// ---------------------------------------------------------------------------
__global__ void split_x_kernel(const float* __restrict__ x) {
    size_t i = ((size_t)blockIdx.x * 256 + threadIdx.x) * 4;
    float4 v = *(const float4*)(x + i);
    __nv_bfloat16 h0 = __float2bfloat16(v.x);
    __nv_bfloat16 h1 = __float2bfloat16(v.y);
    __nv_bfloat16 h2 = __float2bfloat16(v.z);
    __nv_bfloat16 h3 = __float2bfloat16(v.w);
    g_x_hi[i + 0] = h0; g_x_hi[i + 1] = h1; g_x_hi[i + 2] = h2; g_x_hi[i + 3] = h3;
    g_x_lo[i + 0] = __float2bfloat16(v.x - __bfloat162float(h0));
    g_x_lo[i + 1] = __float2bfloat16(v.y - __bfloat162float(h1));
    g_x_lo[i + 2] = __float2bfloat16(v.z - __bfloat162float(h2));
    g_x_lo[i + 3] = __float2bfloat16(v.w - __bfloat162float(h3));
}

// Transpose + split weights: in [E][R][C] f32 -> out [E][C][R] bf16 hi/lo
template<int R, int C, bool W2>
__global__ __launch_bounds__(256) void split_w_kernel(const float* __restrict__ w) {
    __shared__ float tile[32][33];
    const int e  = blockIdx.z;
    const int c0 = blockIdx.x * 32, r0 = blockIdx.y * 32;
    const int tx = threadIdx.x, ty = threadIdx.y;   // 32 x 8
    const float* src = w + ((size_t)e * R + r0) * C + c0;
#pragma unroll
    for (int i = 0; i < 4; i++)
        tile[ty + i * 8][tx] = src[(size_t)(ty + i * 8) * C + tx];
    __syncthreads();
    __nv_bfloat16* ohi = W2 ? g_w2t_hi : g_w1t_hi;
    __nv_bfloat16* olo = W2 ? g_w2t_lo : g_w1t_lo;
    size_t ob = ((size_t)e * C + c0) * R + r0;
#pragma unroll
    for (int i = 0; i < 4; i++) {
        float v = tile[tx][ty + i * 8];
        __nv_bfloat16 hi = __float2bfloat16(v);
        ohi[ob + (size_t)(ty + i * 8) * R + tx] = hi;
        olo[ob + (size_t)(ty + i * 8) * R + tx] = __float2bfloat16(v - __bfloat162float(hi));
    }
}

// ---------------------------------------------------------------------------
// Grouped GEMM via warp-level bf16 HMMA, hi/lo 3-pass split.
// CTA tile M=128 x N=256, K chunk = 64, 2-stage cp.async pipeline.
// 8 warps: warp_m = wid&1 (64 rows), warp_n = wid>>1 (64 cols). Warp tile 64x64.
// Stage: A_hi(16K) | A_lo(16K) | B_hi(32K) | B_lo(32K) = 96K, SW128 swizzle.
#define OFF_ROWS  64u
#define OFF_PROBS 576u
#define OFF_BUF   2048u
#define A_LO_OFF  16384u
#define B_HI_OFF  32768u
#define B_LO_OFF  65536u
#define STAGE_SZ  98304u
#define SMEM_BYTES (OFF_BUF + 2 * STAGE_SZ)

static __device__ __forceinline__ void prefetch_chunk(
    uint32_t sbuf, int k0, int tid,
    const __nv_bfloat16* pa_hi, const __nv_bfloat16* pa_lo,
    const __nv_bfloat16* pb_hi, const __nv_bfloat16* pb_lo) {
    // A: 2 threads per row (128 rows), 4x16B each of hi and lo
    const int arow = tid >> 1;
    const uint32_t abase = (uint32_t)(arow * 128);
#pragma unroll
    for (int j = 0; j < 4; j++) {
        int c16 = (tid & 1) * 4 + j;
        uint32_t d = abase + (uint32_t)((c16 ^ (arow & 7)) << 4);
        cp16(sbuf + d,            pa_hi + k0 + j * 8);
        cp16(sbuf + A_LO_OFF + d, pa_lo + k0 + j * 8);
    }
    // B: 1 thread per row (256 rows), 8x16B each of hi and lo
    const uint32_t bbase = (uint32_t)(tid * 128);
#pragma unroll
    for (int j = 0; j < 8; j++) {
        uint32_t d = bbase + (uint32_t)((j ^ (tid & 7)) << 4);
        cp16(sbuf + B_HI_OFF + d, pb_hi + k0 + j * 8);
        cp16(sbuf + B_LO_OFF + d, pb_lo + k0 + j * 8);
    }
}

template<int KTOT, int NG, bool PHASE2>
__global__ __launch_bounds__(256) void moe_gemm(const float* __restrict__ bias,
                                                float* __restrict__ out) {
    constexpr int NCHUNK = KTOT / 64;
    extern __shared__ char smem[];

    const int e = blockIdx.z;
    const int count = g_cnt[e];
    const int m0 = blockIdx.y * 128;
    if (m0 >= count) return;
    const int n0 = blockIdx.x * 256;
    const int tid = threadIdx.x;
    const int wid = tid >> 5, lane = tid & 31;
    const int warp_m = wid & 1;       // 0..1 -> 64-row block
    const int warp_n = wid >> 1;      // 0..3 -> 64-col block
    const uint32_t sbase = smem_u32(smem);

    int*   rows_s  = (int*)(smem + OFF_ROWS);
    float* probs_s = (float*)(smem + OFF_PROBS);
    if (tid < 128) {
        int m = m0 + tid;
        int idx = e * N_TOK + (m < count ? m : count - 1);
        rows_s[tid]  = g_list[idx];
        probs_s[tid] = g_listp[idx];
    }
    __syncthreads();

    // ---- gather/load pointers ----
    const int arow = tid >> 1;
    const int coff = (tid & 1) * 32;
    const int packed = rows_s[arow];
    size_t abase;
    if (PHASE2) abase = ((size_t)(packed & 1) * N_TOK + (size_t)(packed >> 1)) * (size_t)KTOT;
    else        abase = (size_t)(packed >> 1) * (size_t)KTOT;
    const __nv_bfloat16* Ahi = PHASE2 ? g_h_hi : g_x_hi;
    const __nv_bfloat16* Alo = PHASE2 ? g_h_lo : g_x_lo;
    const __nv_bfloat16* Bhi = PHASE2 ? g_w2t_hi : g_w1t_hi;
    const __nv_bfloat16* Blo = PHASE2 ? g_w2t_lo : g_w1t_lo;
    const __nv_bfloat16* pa_hi = Ahi + abase + coff;
    const __nv_bfloat16* pa_lo = Alo + abase + coff;
    const size_t bbase = ((size_t)e * NG + (size_t)(n0 + tid)) * (size_t)KTOT;
    const __nv_bfloat16* pb_hi = Bhi + bbase;
    const __nv_bfloat16* pb_lo = Blo + bbase;

    // ---- ldmatrix lane geometry ----
    const int a_r  = lane & 15;
    const int a_kb = lane >> 4;
    const int b_r  = (lane & 7) + ((lane >> 4) << 3);
    const int b_kb = (lane >> 3) & 1;

    float acc[4][8][4];
#pragma unroll
    for (int i = 0; i < 4; i++)
#pragma unroll
        for (int j = 0; j < 8; j++)
#pragma unroll
            for (int q = 0; q < 4; q++) acc[i][j][q] = 0.0f;

    prefetch_chunk(sbase + OFF_BUF, 0, tid, pa_hi, pa_lo, pb_hi, pb_lo);
    CP_COMMIT();

    for (int c = 0; c < NCHUNK; c++) {
        if (c + 1 < NCHUNK) {
            prefetch_chunk(sbase + OFF_BUF + (uint32_t)((c + 1) & 1) * STAGE_SZ,
                           (c + 1) * 64, tid, pa_hi, pa_lo, pb_hi, pb_lo);
            CP_COMMIT();
            CP_WAIT1();
        } else {
            CP_WAIT0();
        }
        __syncthreads();

        const uint32_t sb = sbase + OFF_BUF + (uint32_t)(c & 1) * STAGE_SZ;

#pragma unroll
        for (int ks = 0; ks < 4; ks++) {
            uint32_t ah[4][4], bh[8][2];
#pragma unroll
            for (int mf = 0; mf < 4; mf++) {
                int row = warp_m * 64 + mf * 16 + a_r;
                uint32_t off = (uint32_t)(row * 128 + (((2 * ks + a_kb) ^ (row & 7)) << 4));
                ldsm4(ah[mf][0], ah[mf][1], ah[mf][2], ah[mf][3], sb + off);
            }
#pragma unroll
            for (int np = 0; np < 4; np++) {
                int row = warp_n * 64 + np * 16 + b_r;
                uint32_t off = (uint32_t)(row * 128 + (((2 * ks + b_kb) ^ (row & 7)) << 4));
                ldsm4(bh[2 * np][0], bh[2 * np][1], bh[2 * np + 1][0], bh[2 * np + 1][1],
                      sb + B_HI_OFF + off);
            }
#pragma unroll
            for (int mf = 0; mf < 4; mf++)
#pragma unroll
                for (int nf = 0; nf < 8; nf++) mma16816(acc[mf][nf], ah[mf], bh[nf]);

            uint32_t al[4][4];
#pragma unroll
            for (int mf = 0; mf < 4; mf++) {
                int row = warp_m * 64 + mf * 16 + a_r;
                uint32_t off = (uint32_t)(row * 128 + (((2 * ks + a_kb) ^ (row & 7)) << 4));
                ldsm4(al[mf][0], al[mf][1], al[mf][2], al[mf][3], sb + A_LO_OFF + off);
            }
#pragma unroll
            for (int mf = 0; mf < 4; mf++)
#pragma unroll
                for (int nf = 0; nf < 8; nf++) mma16816(acc[mf][nf], al[mf], bh[nf]);

            uint32_t bl[8][2];
#pragma unroll
            for (int np = 0; np < 4; np++) {
                int row = warp_n * 64 + np * 16 + b_r;
                uint32_t off = (uint32_t)(row * 128 + (((2 * ks + b_kb) ^ (row & 7)) << 4));
                ldsm4(bl[2 * np][0], bl[2 * np][1], bl[2 * np + 1][0], bl[2 * np + 1][1],
                      sb + B_LO_OFF + off);
            }
#pragma unroll
            for (int mf = 0; mf < 4; mf++)
#pragma unroll
                for (int nf = 0; nf < 8; nf++) mma16816(acc[mf][nf], ah[mf], bl[nf]);
        }
        __syncthreads();
    }

    // ---- epilogue ----
#pragma unroll
    for (int mf = 0; mf < 4; mf++) {
#pragma unroll
        for (int rr = 0; rr < 2; rr++) {
            const int row = warp_m * 64 + mf * 16 + (lane >> 2) + rr * 8;   // 0..127
            const int m = m0 + row;
            if (m >= count) continue;
            const int pk = rows_s[row];
            if (!PHASE2) {
                const int tok = pk >> 1, slot = pk & 1;
                const size_t hb = ((size_t)slot * N_TOK + (size_t)tok) * FDIM;
#pragma unroll
                for (int nf = 0; nf < 8; nf++) {
#pragma unroll
                    for (int jj = 0; jj < 2; jj++) {
                        const int col = n0 + warp_n * 64 + nf * 8 + 2 * (lane & 3) + jj;
                        float h = acc[mf][nf][rr * 2 + jj] + bias[(size_t)e * NG + col];
                        h = 0.5f * h * (1.0f + erff(h * 0.70710678118654752f));
                        __nv_bfloat16 hh = __float2bfloat16(h);
                        g_h_hi[hb + col] = hh;
                        g_h_lo[hb + col] = __float2bfloat16(h - __bfloat162float(hh));
                    }
                }
            } else {
                const int tok = pk >> 1;
                const float prob = probs_s[row];
                float* orow = out + (size_t)tok * DIM;
#pragma unroll
                for (int nf = 0; nf < 8; nf++) {
#pragma unroll
                    for (int jj = 0; jj < 2; jj++) {
                        const int col = n0 + warp_n * 64 + nf * 8 + 2 * (lane & 3) + jj;
                        float v = (acc[mf][nf][rr * 2 + jj] + bias[(size_t)e * NG + col]) * prob;
                        atomicAdd(orow + col, v);
                    }
                }
            }
        }
    }
}

// ---------------------------------------------------------------------------
__global__ void finalize_kernel(float* __restrict__ out, int out_size) {
    if (out_size <= N_TOK * DIM) return;
    float s = 0.0f;
#pragma unroll
    for (int e = 0; e < NEXP; e++) s += g_tpe[e];
    float loss = 0.0f;
#pragma unroll
    for (int e = 0; e < NEXP; e++)
        loss += g_tpe[e] / (s + 1e-8f) * (g_psum[e] / (float)N_TOK);
    loss *= (float)NEXP;
    out[N_TOK * DIM] = loss;
}

// ---------------------------------------------------------------------------
extern "C" void kernel_launch(void* const* d_in, const int* in_sizes, int n_in,
                              void* d_out, int out_size) {
    const float* x   = (const float*)d_in[0];
    const float* gw  = (const float*)d_in[1];
    const float* w1  = (const float*)d_in[2];
    const float* b1  = (const float*)d_in[3];
    const float* w2  = (const float*)d_in[4];
    const float* b2  = (const float*)d_in[5];
    float* out = (float*)d_out;

    cudaFuncSetAttribute(moe_gemm<DIM, FDIM, false>,
                         cudaFuncAttributeMaxDynamicSharedMemorySize, SMEM_BYTES);
    cudaFuncSetAttribute(moe_gemm<FDIM, DIM, true>,
                         cudaFuncAttributeMaxDynamicSharedMemorySize, SMEM_BYTES);

    zero_kernel<<<(out_size + 255) / 256, 256>>>(out, out_size);
    gate_kernel<<<N_TOK, 128>>>(x, gw);
    split_x_kernel<<<(N_TOK * DIM) / 1024, 256>>>(x);
    split_w_kernel<DIM, FDIM, false><<<dim3(FDIM / 32, DIM / 32, NEXP), dim3(32, 8)>>>(w1);
    split_w_kernel<FDIM, DIM, true><<<dim3(DIM / 32, FDIM / 32, NEXP), dim3(32, 8)>>>(w2);
    moe_gemm<DIM, FDIM, false><<<dim3(FDIM / 256, N_TOK / 128, NEXP), 256, SMEM_BYTES>>>(b1, out);
    moe_gemm<FDIM, DIM, true><<<dim3(DIM / 256, N_TOK / 128, NEXP), 256, SMEM_BYTES>>>(b2, out);
    finalize_kernel<<<1, 1>>>(out, out_size);
}

// round 8
// speedup vs baseline: 1.0846x; 1.0846x over previous
#include <cuda_runtime.h>
#include <cuda_bf16.h>
#include <math.h>
#include <stdint.h>

#define N_TOK 4096
#define DIM   1024
#define FDIM  4096
#define NEXP  8

// ---------------------------------------------------------------------------
// Scratch (static device globals; no runtime allocation)
__device__ __nv_bfloat16 g_x_hi[(size_t)N_TOK * DIM];
__device__ __nv_bfloat16 g_x_lo[(size_t)N_TOK * DIM];
__device__ __nv_bfloat16 g_w1t_hi[(size_t)NEXP * FDIM * DIM];   // [e][f][d]
__device__ __nv_bfloat16 g_w1t_lo[(size_t)NEXP * FDIM * DIM];
__device__ __nv_bfloat16 g_w2t_hi[(size_t)NEXP * DIM * FDIM];   // [e][d][f]
__device__ __nv_bfloat16 g_w2t_lo[(size_t)NEXP * DIM * FDIM];
__device__ __nv_bfloat16 g_h_hi[(size_t)2 * N_TOK * FDIM];      // [slot*N_TOK+tok][f]
__device__ __nv_bfloat16 g_h_lo[(size_t)2 * N_TOK * FDIM];
__device__ int   g_list[NEXP * N_TOK];
__device__ float g_listp[NEXP * N_TOK];
__device__ int   g_cnt[NEXP];
__device__ float g_tpe[NEXP];
__device__ float g_psum[NEXP];

// ---------------------------------------------------------------------------
// PTX helpers (sm_80-era only: cp.async, ldmatrix, mma.sync — valid on sm_100)
static __device__ __forceinline__ uint32_t smem_u32(const void* p) {
    uint32_t a;
    asm("{ .reg .u64 t; cvta.to.shared.u64 t, %1; cvt.u32.u64 %0, t; }" : "=r"(a) : "l"(p));
    return a;
}
static __device__ __forceinline__ void cp16(uint32_t dst, const void* src) {
    asm volatile("cp.async.cg.shared.global [%0], [%1], 16;" :: "r"(dst), "l"(src));
}
#define CP_COMMIT()  asm volatile("cp.async.commit_group;" ::: "memory")
#define CP_WAIT2()   asm volatile("cp.async.wait_group 2;" ::: "memory")

static __device__ __forceinline__ void ldsm4(uint32_t& r0, uint32_t& r1, uint32_t& r2,
                                             uint32_t& r3, uint32_t addr) {
    asm volatile("ldmatrix.sync.aligned.m8n8.x4.shared.b16 {%0,%1,%2,%3}, [%4];"
                 : "=r"(r0), "=r"(r1), "=r"(r2), "=r"(r3) : "r"(addr));
}
static __device__ __forceinline__ void mma16816(float* c, const uint32_t* a, const uint32_t* b) {
    asm volatile(
        "mma.sync.aligned.m16n8k16.row.col.f32.bf16.bf16.f32 "
        "{%0,%1,%2,%3}, {%4,%5,%6,%7}, {%8,%9}, {%0,%1,%2,%3};"
        : "+f"(c[0]), "+f"(c[1]), "+f"(c[2]), "+f"(c[3])
        : "r"(a[0]), "r"(a[1]), "r"(a[2]), "r"(a[3]), "r"(b[0]), "r"(b[1]));
}

// ---------------------------------------------------------------------------
__global__ void zero_kernel(float* __restrict__ out, int out_size) {
    const int n4 = out_size >> 2;
    int i = blockIdx.x * blockDim.x + threadIdx.x;
    if (i < n4) *(float4*)(out + 4 * (size_t)i) = make_float4(0.f, 0.f, 0.f, 0.f);
    if (blockIdx.x == 0 && threadIdx.x == 0) {
        for (int r = n4 * 4; r < out_size; r++) out[r] = 0.0f;
    }
    if (blockIdx.x == 0 && threadIdx.x < NEXP) {
        g_cnt[threadIdx.x]  = 0;
        g_tpe[threadIdx.x]  = 0.0f;
        g_psum[threadIdx.x] = 0.0f;
    }
}

// ---------------------------------------------------------------------------
__global__ __launch_bounds__(128) void gate_kernel(const float* __restrict__ x,
                                                   const float* __restrict__ gw) {
    const int n = blockIdx.x;
    const int t = threadIdx.x;
    float acc[NEXP];
#pragma unroll
    for (int e = 0; e < NEXP; e++) acc[e] = 0.0f;

    const float* xr = x + (size_t)n * DIM;
    for (int i = t; i < DIM; i += 128) {
        float xv = xr[i];
        const float* g = gw + (size_t)i * NEXP;
#pragma unroll
        for (int e = 0; e < NEXP; e++) acc[e] += xv * g[e];
    }

    __shared__ float red[128];
    __shared__ float logits[NEXP];
    for (int e = 0; e < NEXP; e++) {
        red[t] = acc[e];
        __syncthreads();
        for (int s = 64; s > 0; s >>= 1) {
            if (t < s) red[t] += red[t + s];
            __syncthreads();
        }
        if (t == 0) logits[e] = red[0];
        __syncthreads();
    }

    if (t == 0) {
        float mx = logits[0];
#pragma unroll
        for (int e = 1; e < NEXP; e++) mx = fmaxf(mx, logits[e]);
        float p[NEXP];
        float s = 0.0f;
#pragma unroll
        for (int e = 0; e < NEXP; e++) { p[e] = expf(logits[e] - mx); s += p[e]; }
        float inv = 1.0f / s;
#pragma unroll
        for (int e = 0; e < NEXP; e++) {
            p[e] *= inv;
            atomicAdd(&g_psum[e], p[e]);
        }
        int i0 = 0;
#pragma unroll
        for (int e = 1; e < NEXP; e++) if (p[e] > p[i0]) i0 = e;
        int i1 = (i0 == 0) ? 1 : 0;
#pragma unroll
        for (int e = 0; e < NEXP; e++) {
            if (e == i0) continue;
            if (p[e] > p[i1]) i1 = e;
        }
        float ssum = p[i0] + p[i1];
        float pn0 = p[i0] / (ssum + 1e-8f);
        float pn1 = p[i1] / (ssum + 1e-8f);
        atomicAdd(&g_tpe[i0], pn0);
        atomicAdd(&g_tpe[i1], pn1);
        int pos0 = atomicAdd(&g_cnt[i0], 1);
        g_list[i0 * N_TOK + pos0]  = n * 2 + 0;
        g_listp[i0 * N_TOK + pos0] = pn0;
        int pos1 = atomicAdd(&g_cnt[i1], 1);
        g_list[i1 * N_TOK + pos1]  = n * 2 + 1;
        g_listp[i1 * N_TOK + pos1] = pn1;
    }
}

// ---------------------------------------------------------------------------
__global__ void split_x_kernel(const float* __restrict__ x) {
    size_t i = ((size_t)blockIdx.x * 256 + threadIdx.x) * 4;
    float4 v = *(const float4*)(x + i);
    __nv_bfloat16 h0 = __float2bfloat16(v.x);
    __nv_bfloat16 h1 = __float2bfloat16(v.y);
    __nv_bfloat16 h2 = __float2bfloat16(v.z);
    __nv_bfloat16 h3 = __float2bfloat16(v.w);
    g_x_hi[i + 0] = h0; g_x_hi[i + 1] = h1; g_x_hi[i + 2] = h2; g_x_hi[i + 3] = h3;
    g_x_lo[i + 0] = __float2bfloat16(v.x - __bfloat162float(h0));
    g_x_lo[i + 1] = __float2bfloat16(v.y - __bfloat162float(h1));
    g_x_lo[i + 2] = __float2bfloat16(v.z - __bfloat162float(h2));
    g_x_lo[i + 3] = __float2bfloat16(v.w - __bfloat162float(h3));
}

// ---------------------------------------------------------------------------
// Transpose + split weights: in [E][R][C] f32 -> out [E][C][R] bf16 hi/lo.
// 64(R) x 32(C) tile, 256 threads. float4 gmem loads, conflict-free smem
// transpose, 16B bf16 stores.
template<int R, int C, bool W2>
__global__ __launch_bounds__(256) void split_w_kernel(const float* __restrict__ w) {
    __shared__ float tile[32][65];   // [c][r], stride 65 -> conflict-free transpose
    const int e  = blockIdx.z;
    const int c0 = blockIdx.x * 32, r0 = blockIdx.y * 64;
    const int t  = threadIdx.x;

    const int lr  = t >> 2;          // 0..63
    const int lcq = (t & 3) * 8;     // 0,8,16,24
    const float* src = w + ((size_t)e * R + (size_t)(r0 + lr)) * C + c0 + lcq;
    float4 v0 = *(const float4*)src;
    float4 v1 = *(const float4*)(src + 4);
    tile[lcq + 0][lr] = v0.x; tile[lcq + 1][lr] = v0.y;
    tile[lcq + 2][lr] = v0.z; tile[lcq + 3][lr] = v0.w;
    tile[lcq + 4][lr] = v1.x; tile[lcq + 5][lr] = v1.y;
    tile[lcq + 6][lr] = v1.z; tile[lcq + 7][lr] = v1.w;
    __syncthreads();

    const int lc  = t >> 3;          // 0..31
    const int lrq = (t & 7) * 8;     // 0..56
    __align__(16) __nv_bfloat16 hi[8];
    __align__(16) __nv_bfloat16 lo[8];
#pragma unroll
    for (int i = 0; i < 8; i++) {
        float v = tile[lc][lrq + i];
        hi[i] = __float2bfloat16(v);
        lo[i] = __float2bfloat16(v - __bfloat162float(hi[i]));
    }
    __nv_bfloat16* ohi = W2 ? g_w2t_hi : g_w1t_hi;
    __nv_bfloat16* olo = W2 ? g_w2t_lo : g_w1t_lo;
    const size_t ob = ((size_t)e * C + (size_t)(c0 + lc)) * R + r0 + lrq;
    *(uint4*)(ohi + ob) = *(const uint4*)hi;
    *(uint4*)(olo + ob) = *(const uint4*)lo;
}

// ---------------------------------------------------------------------------
// Grouped GEMM via warp-level bf16 HMMA, hi/lo 3-pass split.
// CTA tile M=128 x N=128, K chunk = 64, 3-stage cp.async pipeline.
// 8 warps: warp_m = wid&1 (64 rows), warp_n = wid>>1 (32 cols).
// Stage: A_hi(16K) | A_lo(16K) | B_hi(16K) | B_lo(16K) = 64K, SW128 swizzle.
// Inner loop is PASS-MAJOR: 16 independent mmas per sweep (no acc RAW chains).
#define OFF_ROWS  64u
#define OFF_PROBS 576u
#define OFF_BUF   2048u
#define STAGE_SZ  65536u
#define SMEM_BYTES (OFF_BUF + 3 * STAGE_SZ)

static __device__ __forceinline__ void prefetch_chunk(
    uint32_t sbuf, int k0,
    const __nv_bfloat16* pa_hi, const __nv_bfloat16* pa_lo,
    const __nv_bfloat16* pb_hi, const __nv_bfloat16* pb_lo,
    const uint32_t* dst) {
#pragma unroll
    for (int j = 0; j < 4; j++) cp16(sbuf +      0u + dst[j], pa_hi + k0 + j * 8);
#pragma unroll
    for (int j = 0; j < 4; j++) cp16(sbuf + 16384u + dst[j], pa_lo + k0 + j * 8);
#pragma unroll
    for (int j = 0; j < 4; j++) cp16(sbuf + 32768u + dst[j], pb_hi + k0 + j * 8);
#pragma unroll
    for (int j = 0; j < 4; j++) cp16(sbuf + 49152u + dst[j], pb_lo + k0 + j * 8);
}

template<int KTOT, int NG, bool PHASE2>
__global__ __launch_bounds__(256, 1) void moe_gemm(const float* __restrict__ bias,
                                                   float* __restrict__ out) {
    constexpr int NCHUNK = KTOT / 64;
    extern __shared__ char smem[];

    const int e = blockIdx.z;
    const int count = g_cnt[e];
    const int m0 = blockIdx.y * 128;
    if (m0 >= count) return;
    const int n0 = blockIdx.x * 128;
    const int tid = threadIdx.x;
    const int wid = tid >> 5, lane = tid & 31;
    const int warp_m = wid & 1;       // 0..1 -> 64-row block
    const int warp_n = wid >> 1;      // 0..3 -> 32-col block
    const uint32_t sbase = smem_u32(smem);

    int*   rows_s  = (int*)(smem + OFF_ROWS);
    float* probs_s = (float*)(smem + OFF_PROBS);
    if (tid < 128) {
        int m = m0 + tid;
        int idx = e * N_TOK + (m < count ? m : count - 1);
        rows_s[tid]  = g_list[idx];
        probs_s[tid] = g_listp[idx];
    }
    __syncthreads();

    // ---- gather/load geometry (identical to store-side swizzle) ----
    const int arow = tid >> 1;
    const int coff = (tid & 1) * 32;
    const int packed = rows_s[arow];
    size_t abase;
    if (PHASE2) abase = ((size_t)(packed & 1) * N_TOK + (size_t)(packed >> 1)) * (size_t)KTOT;
    else        abase = (size_t)(packed >> 1) * (size_t)KTOT;
    const __nv_bfloat16* Ahi = PHASE2 ? g_h_hi : g_x_hi;
    const __nv_bfloat16* Alo = PHASE2 ? g_h_lo : g_x_lo;
    const __nv_bfloat16* Bhi = PHASE2 ? g_w2t_hi : g_w1t_hi;
    const __nv_bfloat16* Blo = PHASE2 ? g_w2t_lo : g_w1t_lo;
    const __nv_bfloat16* pa_hi = Ahi + abase + coff;
    const __nv_bfloat16* pa_lo = Alo + abase + coff;
    const size_t bbase = ((size_t)e * NG + (size_t)(n0 + arow)) * (size_t)KTOT + coff;
    const __nv_bfloat16* pb_hi = Bhi + bbase;
    const __nv_bfloat16* pb_lo = Blo + bbase;

    uint32_t dst[4];
#pragma unroll
    for (int j = 0; j < 4; j++) {
        int c16 = (tid & 1) * 4 + j;
        dst[j] = (uint32_t)(arow * 128 + ((c16 ^ (arow & 7)) * 16));
    }

    // ---- ldmatrix address components ----
    const int a_r  = lane & 15;
    const int a_kb = lane >> 4;
    const int b_r  = (lane & 7) + ((lane >> 4) << 3);
    const int b_kb = (lane >> 3) & 1;

    float acc[4][4][4];
#pragma unroll
    for (int i = 0; i < 4; i++)
#pragma unroll
        for (int j = 0; j < 4; j++)
#pragma unroll
            for (int q = 0; q < 4; q++) acc[i][j][q] = 0.0f;

    // Prologue: prefetch chunks 0,1
    prefetch_chunk(sbase + OFF_BUF + 0 * STAGE_SZ, 0,  pa_hi, pa_lo, pb_hi, pb_lo, dst);
    CP_COMMIT();
    prefetch_chunk(sbase + OFF_BUF + 1 * STAGE_SZ, 64, pa_hi, pa_lo, pb_hi, pb_lo, dst);
    CP_COMMIT();

    for (int c = 0; c < NCHUNK; c++) {
        if (c + 2 < NCHUNK)
            prefetch_chunk(sbase + OFF_BUF + (uint32_t)((c + 2) % 3) * STAGE_SZ, (c + 2) * 64,
                           pa_hi, pa_lo, pb_hi, pb_lo, dst);
        CP_COMMIT();
        CP_WAIT2();
        __syncthreads();

        const uint32_t sb   = sbase + OFF_BUF + (uint32_t)(c % 3) * STAGE_SZ;
        const uint32_t sAhi = sb, sAlo = sb + 16384u, sBhi = sb + 32768u, sBlo = sb + 49152u;

#pragma unroll
        for (int ks = 0; ks < 4; ks++) {
            uint32_t ah[4][4], al[4][4], bh[4][2], bl[4][2];
#pragma unroll
            for (int mf = 0; mf < 4; mf++) {
                int row = warp_m * 64 + mf * 16 + a_r;
                uint32_t off = (uint32_t)(row * 128 + (((2 * ks + a_kb) ^ (row & 7)) << 4));
                ldsm4(ah[mf][0], ah[mf][1], ah[mf][2], ah[mf][3], sAhi + off);
                ldsm4(al[mf][0], al[mf][1], al[mf][2], al[mf][3], sAlo + off);
            }
#pragma unroll
            for (int np = 0; np < 2; np++) {
                int row = warp_n * 32 + np * 16 + b_r;
                uint32_t off = (uint32_t)(row * 128 + (((2 * ks + b_kb) ^ (row & 7)) << 4));
                ldsm4(bh[2 * np][0], bh[2 * np][1], bh[2 * np + 1][0], bh[2 * np + 1][1], sBhi + off);
                ldsm4(bl[2 * np][0], bl[2 * np][1], bl[2 * np + 1][0], bl[2 * np + 1][1], sBlo + off);
            }
            // PASS-MAJOR sweeps: each sweep = 16 independent accumulators
#pragma unroll
            for (int mf = 0; mf < 4; mf++)
#pragma unroll
                for (int nf = 0; nf < 4; nf++) mma16816(acc[mf][nf], ah[mf], bh[nf]);
#pragma unroll
            for (int mf = 0; mf < 4; mf++)
#pragma unroll
                for (int nf = 0; nf < 4; nf++) mma16816(acc[mf][nf], al[mf], bh[nf]);
#pragma unroll
            for (int mf = 0; mf < 4; mf++)
#pragma unroll
                for (int nf = 0; nf < 4; nf++) mma16816(acc[mf][nf], ah[mf], bl[nf]);
        }
        __syncthreads();
    }

    // ---- epilogue ----
#pragma unroll
    for (int mf = 0; mf < 4; mf++) {
#pragma unroll
        for (int rr = 0; rr < 2; rr++) {
            const int row = warp_m * 64 + mf * 16 + (lane >> 2) + rr * 8;   // 0..127
            const int m = m0 + row;
            if (m >= count) continue;
            const int pk = rows_s[row];
            if (!PHASE2) {
                const int tok = pk >> 1, slot = pk & 1;
                const size_t hb = ((size_t)slot * N_TOK + (size_t)tok) * FDIM;
#pragma unroll
                for (int nf = 0; nf < 4; nf++) {
#pragma unroll
                    for (int jj = 0; jj < 2; jj++) {
                        const int col = n0 + warp_n * 32 + nf * 8 + 2 * (lane & 3) + jj;
                        float h = acc[mf][nf][rr * 2 + jj] + bias[(size_t)e * NG + col];
                        h = 0.5f * h * (1.0f + erff(h * 0.70710678118654752f));
                        __nv_bfloat16 hh = __float2bfloat16(h);
                        g_h_hi[hb + col] = hh;
                        g_h_lo[hb + col] = __float2bfloat16(h - __bfloat162float(hh));
                    }
                }
            } else {
                const int tok = pk >> 1;
                const float prob = probs_s[row];
                float* orow = out + (size_t)tok * DIM;
#pragma unroll
                for (int nf = 0; nf < 4; nf++) {
#pragma unroll
                    for (int jj = 0; jj < 2; jj++) {
                        const int col = n0 + warp_n * 32 + nf * 8 + 2 * (lane & 3) + jj;
                        float v = (acc[mf][nf][rr * 2 + jj] + bias[(size_t)e * NG + col]) * prob;
                        atomicAdd(orow + col, v);
                    }
                }
            }
        }
    }
}

// ---------------------------------------------------------------------------
__global__ void finalize_kernel(float* __restrict__ out, int out_size) {
    if (out_size <= N_TOK * DIM) return;
    float s = 0.0f;
#pragma unroll
    for (int e = 0; e < NEXP; e++) s += g_tpe[e];
    float loss = 0.0f;
#pragma unroll
    for (int e = 0; e < NEXP; e++)
        loss += g_tpe[e] / (s + 1e-8f) * (g_psum[e] / (float)N_TOK);
    loss *= (float)NEXP;
    out[N_TOK * DIM] = loss;
}

// ---------------------------------------------------------------------------
extern "C" void kernel_launch(void* const* d_in, const int* in_sizes, int n_in,
                              void* d_out, int out_size) {
    const float* x   = (const float*)d_in[0];
    const float* gw  = (const float*)d_in[1];
    const float* w1  = (const float*)d_in[2];
    const float* b1  = (const float*)d_in[3];
    const float* w2  = (const float*)d_in[4];
    const float* b2  = (const float*)d_in[5];
    float* out = (float*)d_out;

    cudaFuncSetAttribute(moe_gemm<DIM, FDIM, false>,
                         cudaFuncAttributeMaxDynamicSharedMemorySize, SMEM_BYTES);
    cudaFuncSetAttribute(moe_gemm<FDIM, DIM, true>,
                         cudaFuncAttributeMaxDynamicSharedMemorySize, SMEM_BYTES);

    zero_kernel<<<((out_size >> 2) + 255) / 256, 256>>>(out, out_size);
    gate_kernel<<<N_TOK, 128>>>(x, gw);
    split_x_kernel<<<(N_TOK * DIM) / 1024, 256>>>(x);
    split_w_kernel<DIM, FDIM, false><<<dim3(FDIM / 32, DIM / 64, NEXP), 256>>>(w1);
    split_w_kernel<FDIM, DIM, true><<<dim3(DIM / 32, FDIM / 64, NEXP), 256>>>(w2);
    moe_gemm<DIM, FDIM, false><<<dim3(FDIM / 128, N_TOK / 128, NEXP), 256, SMEM_BYTES>>>(b1, out);
    moe_gemm<FDIM, DIM, true><<<dim3(DIM / 128, N_TOK / 128, NEXP), 256, SMEM_BYTES>>>(b2, out);
    finalize_kernel<<<1, 1>>>(out, out_size);
}

// round 9
// speedup vs baseline: 1.0857x; 1.0010x over previous
#include <cuda_runtime.h>
#include <cuda_bf16.h>
#include <math.h>
#include <stdint.h>

#define N_TOK 4096
#define DIM   1024
#define FDIM  4096
#define NEXP  8

// ---------------------------------------------------------------------------
// Scratch (static device globals; no runtime allocation)
__device__ __nv_bfloat16 g_x_hi[(size_t)N_TOK * DIM];
__device__ __nv_bfloat16 g_x_lo[(size_t)N_TOK * DIM];
__device__ __nv_bfloat16 g_w1t_hi[(size_t)NEXP * FDIM * DIM];   // [e][f][d]
__device__ __nv_bfloat16 g_w1t_lo[(size_t)NEXP * FDIM * DIM];
__device__ __nv_bfloat16 g_w2t_hi[(size_t)NEXP * DIM * FDIM];   // [e][d][f]
__device__ __nv_bfloat16 g_w2t_lo[(size_t)NEXP * DIM * FDIM];
__device__ __nv_bfloat16 g_h_hi[(size_t)2 * N_TOK * FDIM];      // [slot*N_TOK+tok][f]
__device__ __nv_bfloat16 g_h_lo[(size_t)2 * N_TOK * FDIM];
__device__ int   g_list[NEXP * N_TOK];
__device__ float g_listp[NEXP * N_TOK];
__device__ int   g_cnt[NEXP];
__device__ float g_tpe[NEXP];
__device__ float g_psum[NEXP];

// ---------------------------------------------------------------------------
// PTX helpers (sm_80-era only: cp.async, ldmatrix, mma.sync — valid on sm_100)
static __device__ __forceinline__ uint32_t smem_u32(const void* p) {
    uint32_t a;
    asm("{ .reg .u64 t; cvta.to.shared.u64 t, %1; cvt.u32.u64 %0, t; }" : "=r"(a) : "l"(p));
    return a;
}
static __device__ __forceinline__ void cp16(uint32_t dst, const void* src) {
    asm volatile("cp.async.cg.shared.global [%0], [%1], 16;" :: "r"(dst), "l"(src));
}
#define CP_COMMIT()  asm volatile("cp.async.commit_group;" ::: "memory")
#define CP_WAIT2()   asm volatile("cp.async.wait_group 2;" ::: "memory")

static __device__ __forceinline__ void ldsm4(uint32_t& r0, uint32_t& r1, uint32_t& r2,
                                             uint32_t& r3, uint32_t addr) {
    asm volatile("ldmatrix.sync.aligned.m8n8.x4.shared.b16 {%0,%1,%2,%3}, [%4];"
                 : "=r"(r0), "=r"(r1), "=r"(r2), "=r"(r3) : "r"(addr));
}
static __device__ __forceinline__ void mma16816(float* c, const uint32_t* a, const uint32_t* b) {
    asm volatile(
        "mma.sync.aligned.m16n8k16.row.col.f32.bf16.bf16.f32 "
        "{%0,%1,%2,%3}, {%4,%5,%6,%7}, {%8,%9}, {%0,%1,%2,%3};"
        : "+f"(c[0]), "+f"(c[1]), "+f"(c[2]), "+f"(c[3])
        : "r"(a[0]), "r"(a[1]), "r"(a[2]), "r"(a[3]), "r"(b[0]), "r"(b[1]));
}

// ---------------------------------------------------------------------------
__global__ void zero_kernel(float* __restrict__ out, int out_size) {
    const int n4 = out_size >> 2;
    int i = blockIdx.x * blockDim.x + threadIdx.x;
    if (i < n4) *(float4*)(out + 4 * (size_t)i) = make_float4(0.f, 0.f, 0.f, 0.f);
    if (blockIdx.x == 0 && threadIdx.x == 0) {
        for (int r = n4 * 4; r < out_size; r++) out[r] = 0.0f;
    }
    if (blockIdx.x == 0 && threadIdx.x < NEXP) {
        g_cnt[threadIdx.x]  = 0;
        g_tpe[threadIdx.x]  = 0.0f;
        g_psum[threadIdx.x] = 0.0f;
    }
}

// ---------------------------------------------------------------------------
__global__ __launch_bounds__(128) void gate_kernel(const float* __restrict__ x,
                                                   const float* __restrict__ gw) {
    const int n = blockIdx.x;
    const int t = threadIdx.x;
    float acc[NEXP];
#pragma unroll
    for (int e = 0; e < NEXP; e++) acc[e] = 0.0f;

    const float* xr = x + (size_t)n * DIM;
    for (int i = t; i < DIM; i += 128) {
        float xv = xr[i];
        const float* g = gw + (size_t)i * NEXP;
#pragma unroll
        for (int e = 0; e < NEXP; e++) acc[e] += xv * g[e];
    }

    __shared__ float red[128];
    __shared__ float logits[NEXP];
    for (int e = 0; e < NEXP; e++) {
        red[t] = acc[e];
        __syncthreads();
        for (int s = 64; s > 0; s >>= 1) {
            if (t < s) red[t] += red[t + s];
            __syncthreads();
        }
        if (t == 0) logits[e] = red[0];
        __syncthreads();
    }

    if (t == 0) {
        float mx = logits[0];
#pragma unroll
        for (int e = 1; e < NEXP; e++) mx = fmaxf(mx, logits[e]);
        float p[NEXP];
        float s = 0.0f;
#pragma unroll
        for (int e = 0; e < NEXP; e++) { p[e] = expf(logits[e] - mx); s += p[e]; }
        float inv = 1.0f / s;
#pragma unroll
        for (int e = 0; e < NEXP; e++) {
            p[e] *= inv;
            atomicAdd(&g_psum[e], p[e]);
        }
        int i0 = 0;
#pragma unroll
        for (int e = 1; e < NEXP; e++) if (p[e] > p[i0]) i0 = e;
        int i1 = (i0 == 0) ? 1 : 0;
#pragma unroll
        for (int e = 0; e < NEXP; e++) {
            if (e == i0) continue;
            if (p[e] > p[i1]) i1 = e;
        }
        float ssum = p[i0] + p[i1];
        float pn0 = p[i0] / (ssum + 1e-8f);
        float pn1 = p[i1] / (ssum + 1e-8f);
        atomicAdd(&g_tpe[i0], pn0);
        atomicAdd(&g_tpe[i1], pn1);
        int pos0 = atomicAdd(&g_cnt[i0], 1);
        g_list[i0 * N_TOK + pos0]  = n * 2 + 0;
        g_listp[i0 * N_TOK + pos0] = pn0;
        int pos1 = atomicAdd(&g_cnt[i1], 1);
        g_list[i1 * N_TOK + pos1]  = n * 2 + 1;
        g_listp[i1 * N_TOK + pos1] = pn1;
    }
}

// ---------------------------------------------------------------------------
__global__ void split_x_kernel(const float* __restrict__ x) {
    size_t i = ((size_t)blockIdx.x * 256 + threadIdx.x) * 4;
    float4 v = *(const float4*)(x + i);
    __nv_bfloat16 h0 = __float2bfloat16(v.x);
    __nv_bfloat16 h1 = __float2bfloat16(v.y);
    __nv_bfloat16 h2 = __float2bfloat16(v.z);
    __nv_bfloat16 h3 = __float2bfloat16(v.w);
    g_x_hi[i + 0] = h0; g_x_hi[i + 1] = h1; g_x_hi[i + 2] = h2; g_x_hi[i + 3] = h3;
    g_x_lo[i + 0] = __float2bfloat16(v.x - __bfloat162float(h0));
    g_x_lo[i + 1] = __float2bfloat16(v.y - __bfloat162float(h1));
    g_x_lo[i + 2] = __float2bfloat16(v.z - __bfloat162float(h2));
    g_x_lo[i + 3] = __float2bfloat16(v.w - __bfloat162float(h3));
}

// ---------------------------------------------------------------------------
// Transpose + split weights: in [E][R][C] f32 -> out [E][C][R] bf16 hi/lo.
// 64(R) x 32(C) tile, 256 threads. float4 gmem loads, conflict-free smem
// transpose, 16B bf16 stores.
template<int R, int C, bool W2>
__global__ __launch_bounds__(256) void split_w_kernel(const float* __restrict__ w) {
    __shared__ float tile[32][65];   // [c][r], stride 65 -> conflict-free transpose
    const int e  = blockIdx.z;
    const int c0 = blockIdx.x * 32, r0 = blockIdx.y * 64;
    const int t  = threadIdx.x;

    const int lr  = t >> 2;          // 0..63
    const int lcq = (t & 3) * 8;     // 0,8,16,24
    const float* src = w + ((size_t)e * R + (size_t)(r0 + lr)) * C + c0 + lcq;
    float4 v0 = *(const float4*)src;
    float4 v1 = *(const float4*)(src + 4);
    tile[lcq + 0][lr] = v0.x; tile[lcq + 1][lr] = v0.y;
    tile[lcq + 2][lr] = v0.z; tile[lcq + 3][lr] = v0.w;
    tile[lcq + 4][lr] = v1.x; tile[lcq + 5][lr] = v1.y;
    tile[lcq + 6][lr] = v1.z; tile[lcq + 7][lr] = v1.w;
    __syncthreads();

    const int lc  = t >> 3;          // 0..31
    const int lrq = (t & 7) * 8;     // 0..56
    __align__(16) __nv_bfloat16 hi[8];
    __align__(16) __nv_bfloat16 lo[8];
#pragma unroll
    for (int i = 0; i < 8; i++) {
        float v = tile[lc][lrq + i];
        hi[i] = __float2bfloat16(v);
        lo[i] = __float2bfloat16(v - __bfloat162float(hi[i]));
    }
    __nv_bfloat16* ohi = W2 ? g_w2t_hi : g_w1t_hi;
    __nv_bfloat16* olo = W2 ? g_w2t_lo : g_w1t_lo;
    const size_t ob = ((size_t)e * C + (size_t)(c0 + lc)) * R + r0 + lrq;
    *(uint4*)(ohi + ob) = *(const uint4*)hi;
    *(uint4*)(olo + ob) = *(const uint4*)lo;
}

// ---------------------------------------------------------------------------
// Grouped GEMM via warp-level bf16 HMMA, hi/lo 3-pass split.
// CTA tile M=128 x N=128, K chunk = 64, 3-stage cp.async pipeline.
// 8 warps: warp_m = wid&1 (64 rows), warp_n = wid>>1 (32 cols).
// Stage: A_hi(16K) | A_lo(16K) | B_hi(16K) | B_lo(16K) = 64K, SW128 swizzle.
// Inner loop is PASS-MAJOR: 16 independent mmas per sweep (no acc RAW chains).
#define OFF_ROWS  64u
#define OFF_PROBS 576u
#define OFF_BUF   2048u
#define STAGE_SZ  65536u
#define SMEM_BYTES (OFF_BUF + 3 * STAGE_SZ)

static __device__ __forceinline__ void prefetch_chunk(
    uint32_t sbuf, int k0,
    const __nv_bfloat16* pa_hi, const __nv_bfloat16* pa_lo,
    const __nv_bfloat16* pb_hi, const __nv_bfloat16* pb_lo,
    const uint32_t* dst) {
#pragma unroll
    for (int j = 0; j < 4; j++) cp16(sbuf +      0u + dst[j], pa_hi + k0 + j * 8);
#pragma unroll
    for (int j = 0; j < 4; j++) cp16(sbuf + 16384u + dst[j], pa_lo + k0 + j * 8);
#pragma unroll
    for (int j = 0; j < 4; j++) cp16(sbuf + 32768u + dst[j], pb_hi + k0 + j * 8);
#pragma unroll
    for (int j = 0; j < 4; j++) cp16(sbuf + 49152u + dst[j], pb_lo + k0 + j * 8);
}

template<int KTOT, int NG, bool PHASE2>
__global__ __launch_bounds__(256, 1) void moe_gemm(const float* __restrict__ bias,
                                                   float* __restrict__ out) {
    constexpr int NCHUNK = KTOT / 64;
    extern __shared__ char smem[];

    const int e = blockIdx.z;
    const int count = g_cnt[e];
    const int m0 = blockIdx.y * 128;
    if (m0 >= count) return;
    const int n0 = blockIdx.x * 128;
    const int tid = threadIdx.x;
    const int wid = tid >> 5, lane = tid & 31;
    const int warp_m = wid & 1;       // 0..1 -> 64-row block
    const int warp_n = wid >> 1;      // 0..3 -> 32-col block
    const uint32_t sbase = smem_u32(smem);

    int*   rows_s  = (int*)(smem + OFF_ROWS);
    float* probs_s = (float*)(smem + OFF_PROBS);
    if (tid < 128) {
        int m = m0 + tid;
        int idx = e * N_TOK + (m < count ? m : count - 1);
        rows_s[tid]  = g_list[idx];
        probs_s[tid] = g_listp[idx];
    }
    __syncthreads();

    // ---- gather/load geometry (identical to store-side swizzle) ----
    const int arow = tid >> 1;
    const int coff = (tid & 1) * 32;
    const int packed = rows_s[arow];
    size_t abase;
    if (PHASE2) abase = ((size_t)(packed & 1) * N_TOK + (size_t)(packed >> 1)) * (size_t)KTOT;
    else        abase = (size_t)(packed >> 1) * (size_t)KTOT;
    const __nv_bfloat16* Ahi = PHASE2 ? g_h_hi : g_x_hi;
    const __nv_bfloat16* Alo = PHASE2 ? g_h_lo : g_x_lo;
    const __nv_bfloat16* Bhi = PHASE2 ? g_w2t_hi : g_w1t_hi;
    const __nv_bfloat16* Blo = PHASE2 ? g_w2t_lo : g_w1t_lo;
    const __nv_bfloat16* pa_hi = Ahi + abase + coff;
    const __nv_bfloat16* pa_lo = Alo + abase + coff;
    const size_t bbase = ((size_t)e * NG + (size_t)(n0 + arow)) * (size_t)KTOT + coff;
    const __nv_bfloat16* pb_hi = Bhi + bbase;
    const __nv_bfloat16* pb_lo = Blo + bbase;

    uint32_t dst[4];
#pragma unroll
    for (int j = 0; j < 4; j++) {
        int c16 = (tid & 1) * 4 + j;
        dst[j] = (uint32_t)(arow * 128 + ((c16 ^ (arow & 7)) * 16));
    }

    // ---- ldmatrix address components ----
    const int a_r  = lane & 15;
    const int a_kb = lane >> 4;
    const int b_r  = (lane & 7) + ((lane >> 4) << 3);
    const int b_kb = (lane >> 3) & 1;

    float acc[4][4][4];
#pragma unroll
    for (int i = 0; i < 4; i++)
#pragma unroll
        for (int j = 0; j < 4; j++)
#pragma unroll
            for (int q = 0; q < 4; q++) acc[i][j][q] = 0.0f;

    // Prologue: prefetch chunks 0,1
    prefetch_chunk(sbase + OFF_BUF + 0 * STAGE_SZ, 0,  pa_hi, pa_lo, pb_hi, pb_lo, dst);
    CP_COMMIT();
    prefetch_chunk(sbase + OFF_BUF + 1 * STAGE_SZ, 64, pa_hi, pa_lo, pb_hi, pb_lo, dst);
    CP_COMMIT();

    for (int c = 0; c < NCHUNK; c++) {
        if (c + 2 < NCHUNK)
            prefetch_chunk(sbase + OFF_BUF + (uint32_t)((c + 2) % 3) * STAGE_SZ, (c + 2) * 64,
                           pa_hi, pa_lo, pb_hi, pb_lo, dst);
        CP_COMMIT();
        CP_WAIT2();
        __syncthreads();

        const uint32_t sb   = sbase + OFF_BUF + (uint32_t)(c % 3) * STAGE_SZ;
        const uint32_t sAhi = sb, sAlo = sb + 16384u, sBhi = sb + 32768u, sBlo = sb + 49152u;

#pragma unroll
        for (int ks = 0; ks < 4; ks++) {
            uint32_t ah[4][4], al[4][4], bh[4][2], bl[4][2];
#pragma unroll
            for (int mf = 0; mf < 4; mf++) {
                int row = warp_m * 64 + mf * 16 + a_r;
                uint32_t off = (uint32_t)(row * 128 + (((2 * ks + a_kb) ^ (row & 7)) << 4));
                ldsm4(ah[mf][0], ah[mf][1], ah[mf][2], ah[mf][3], sAhi + off);
                ldsm4(al[mf][0], al[mf][1], al[mf][2], al[mf][3], sAlo + off);
            }
#pragma unroll
            for (int np = 0; np < 2; np++) {
                int row = warp_n * 32 + np * 16 + b_r;
                uint32_t off = (uint32_t)(row * 128 + (((2 * ks + b_kb) ^ (row & 7)) << 4));
                ldsm4(bh[2 * np][0], bh[2 * np][1], bh[2 * np + 1][0], bh[2 * np + 1][1], sBhi + off);
                ldsm4(bl[2 * np][0], bl[2 * np][1], bl[2 * np + 1][0], bl[2 * np + 1][1], sBlo + off);
            }
            // PASS-MAJOR sweeps: each sweep = 16 independent accumulators
#pragma unroll
            for (int mf = 0; mf < 4; mf++)
#pragma unroll
                for (int nf = 0; nf < 4; nf++) mma16816(acc[mf][nf], ah[mf], bh[nf]);
#pragma unroll
            for (int mf = 0; mf < 4; mf++)
#pragma unroll
                for (int nf = 0; nf < 4; nf++) mma16816(acc[mf][nf], al[mf], bh[nf]);
#pragma unroll
            for (int mf = 0; mf < 4; mf++)
#pragma unroll
                for (int nf = 0; nf < 4; nf++) mma16816(acc[mf][nf], ah[mf], bl[nf]);
        }
        __syncthreads();
    }

    // ---- epilogue ----
#pragma unroll
    for (int mf = 0; mf < 4; mf++) {
#pragma unroll
        for (int rr = 0; rr < 2; rr++) {
            const int row = warp_m * 64 + mf * 16 + (lane >> 2) + rr * 8;   // 0..127
            const int m = m0 + row;
            if (m >= count) continue;
            const int pk = rows_s[row];
            if (!PHASE2) {
                const int tok = pk >> 1, slot = pk & 1;
                const size_t hb = ((size_t)slot * N_TOK + (size_t)tok) * FDIM;
#pragma unroll
                for (int nf = 0; nf < 4; nf++) {
#pragma unroll
                    for (int jj = 0; jj < 2; jj++) {
                        const int col = n0 + warp_n * 32 + nf * 8 + 2 * (lane & 3) + jj;
                        float h = acc[mf][nf][rr * 2 + jj] + bias[(size_t)e * NG + col];
                        h = 0.5f * h * (1.0f + erff(h * 0.70710678118654752f));
                        __nv_bfloat16 hh = __float2bfloat16(h);
                        g_h_hi[hb + col] = hh;
                        g_h_lo[hb + col] = __float2bfloat16(h - __bfloat162float(hh));
                    }
                }
            } else {
                const int tok = pk >> 1;
                const float prob = probs_s[row];
                float* orow = out + (size_t)tok * DIM;
#pragma unroll
                for (int nf = 0; nf < 4; nf++) {
#pragma unroll
                    for (int jj = 0; jj < 2; jj++) {
                        const int col = n0 + warp_n * 32 + nf * 8 + 2 * (lane & 3) + jj;
                        float v = (acc[mf][nf][rr * 2 + jj] + bias[(size_t)e * NG + col]) * prob;
                        atomicAdd(orow + col, v);
                    }
                }
            }
        }
    }
}

// ---------------------------------------------------------------------------
__global__ void finalize_kernel(float* __restrict__ out, int out_size) {
    if (out_size <= N_TOK * DIM) return;
    float s = 0.0f;
#pragma unroll
    for (int e = 0; e < NEXP; e++) s += g_tpe[e];
    float loss = 0.0f;
#pragma unroll
    for (int e = 0; e < NEXP; e++)
        loss += g_tpe[e] / (s + 1e-8f) * (g_psum[e] / (float)N_TOK);
    loss *= (float)NEXP;
    out[N_TOK * DIM] = loss;
}

// ---------------------------------------------------------------------------
extern "C" void kernel_launch(void* const* d_in, const int* in_sizes, int n_in,
                              void* d_out, int out_size) {
    const float* x   = (const float*)d_in[0];
    const float* gw  = (const float*)d_in[1];
    const float* w1  = (const float*)d_in[2];
    const float* b1  = (const float*)d_in[3];
    const float* w2  = (const float*)d_in[4];
    const float* b2  = (const float*)d_in[5];
    float* out = (float*)d_out;

    cudaFuncSetAttribute(moe_gemm<DIM, FDIM, false>,
                         cudaFuncAttributeMaxDynamicSharedMemorySize, SMEM_BYTES);
    cudaFuncSetAttribute(moe_gemm<FDIM, DIM, true>,
                         cudaFuncAttributeMaxDynamicSharedMemorySize, SMEM_BYTES);

    zero_kernel<<<((out_size >> 2) + 255) / 256, 256>>>(out, out_size);
    gate_kernel<<<N_TOK, 128>>>(x, gw);
    split_x_kernel<<<(N_TOK * DIM) / 1024, 256>>>(x);
    split_w_kernel<DIM, FDIM, false><<<dim3(FDIM / 32, DIM / 64, NEXP), 256>>>(w1);
    split_w_kernel<FDIM, DIM, true><<<dim3(DIM / 32, FDIM / 64, NEXP), 256>>>(w2);
    moe_gemm<DIM, FDIM, false><<<dim3(FDIM / 128, N_TOK / 128, NEXP), 256, SMEM_BYTES>>>(b1, out);
    moe_gemm<FDIM, DIM, true><<<dim3(DIM / 128, N_TOK / 128, NEXP), 256, SMEM_BYTES>>>(b2, out);
    finalize_kernel<<<1, 1>>>(out, out_size);
}

// round 10
// speedup vs baseline: 2.4835x; 2.2874x over previous
#include <cuda_runtime.h>
#include <cuda_fp16.h>
#include <math.h>
#include <stdint.h>

#define N_TOK 4096
#define DIM   1024
#define FDIM  4096
#define NEXP  8

// ---------------------------------------------------------------------------
// Scratch (static device globals; no runtime allocation)
__device__ __half g_x_h[(size_t)N_TOK * DIM];
__device__ __half g_w1t[(size_t)NEXP * FDIM * DIM];   // [e][f][d]
__device__ __half g_w2t[(size_t)NEXP * DIM * FDIM];   // [e][d][f]
__device__ __half g_h[(size_t)2 * N_TOK * FDIM];      // [slot*N_TOK+tok][f]
__device__ int   g_list[NEXP * N_TOK];
__device__ float g_listp[NEXP * N_TOK];
__device__ int   g_cnt[NEXP];
__device__ float g_tpe[NEXP];
__device__ float g_psum[NEXP];

// ---------------------------------------------------------------------------
// PTX helpers (sm_80-era only: cp.async, ldmatrix, mma.sync — valid on sm_100)
static __device__ __forceinline__ uint32_t smem_u32(const void* p) {
    uint32_t a;
    asm("{ .reg .u64 t; cvta.to.shared.u64 t, %1; cvt.u32.u64 %0, t; }" : "=r"(a) : "l"(p));
    return a;
}
static __device__ __forceinline__ void cp16(uint32_t dst, const void* src) {
    asm volatile("cp.async.cg.shared.global [%0], [%1], 16;" :: "r"(dst), "l"(src));
}
#define CP_COMMIT()  asm volatile("cp.async.commit_group;" ::: "memory")
#define CP_WAIT2()   asm volatile("cp.async.wait_group 2;" ::: "memory")

static __device__ __forceinline__ void ldsm4(uint32_t& r0, uint32_t& r1, uint32_t& r2,
                                             uint32_t& r3, uint32_t addr) {
    asm volatile("ldmatrix.sync.aligned.m8n8.x4.shared.b16 {%0,%1,%2,%3}, [%4];"
                 : "=r"(r0), "=r"(r1), "=r"(r2), "=r"(r3) : "r"(addr));
}
static __device__ __forceinline__ void mma16816(float* c, const uint32_t* a, const uint32_t* b) {
    asm volatile(
        "mma.sync.aligned.m16n8k16.row.col.f32.f16.f16.f32 "
        "{%0,%1,%2,%3}, {%4,%5,%6,%7}, {%8,%9}, {%0,%1,%2,%3};"
        : "+f"(c[0]), "+f"(c[1]), "+f"(c[2]), "+f"(c[3])
        : "r"(a[0]), "r"(a[1]), "r"(a[2]), "r"(a[3]), "r"(b[0]), "r"(b[1]));
}

// ---------------------------------------------------------------------------
__global__ void zero_kernel(float* __restrict__ out, int out_size) {
    const int n4 = out_size >> 2;
    int i = blockIdx.x * blockDim.x + threadIdx.x;
    if (i < n4) *(float4*)(out + 4 * (size_t)i) = make_float4(0.f, 0.f, 0.f, 0.f);
    if (blockIdx.x == 0 && threadIdx.x == 0) {
        for (int r = n4 * 4; r < out_size; r++) out[r] = 0.0f;
    }
    if (blockIdx.x == 0 && threadIdx.x < NEXP) {
        g_cnt[threadIdx.x]  = 0;
        g_tpe[threadIdx.x]  = 0.0f;
        g_psum[threadIdx.x] = 0.0f;
    }
}

// ---------------------------------------------------------------------------
__global__ __launch_bounds__(128) void gate_kernel(const float* __restrict__ x,
                                                   const float* __restrict__ gw) {
    const int n = blockIdx.x;
    const int t = threadIdx.x;
    float acc[NEXP];
#pragma unroll
    for (int e = 0; e < NEXP; e++) acc[e] = 0.0f;

    const float* xr = x + (size_t)n * DIM;
    for (int i = t; i < DIM; i += 128) {
        float xv = xr[i];
        const float* g = gw + (size_t)i * NEXP;
#pragma unroll
        for (int e = 0; e < NEXP; e++) acc[e] += xv * g[e];
    }

    __shared__ float red[128];
    __shared__ float logits[NEXP];
    for (int e = 0; e < NEXP; e++) {
        red[t] = acc[e];
        __syncthreads();
        for (int s = 64; s > 0; s >>= 1) {
            if (t < s) red[t] += red[t + s];
            __syncthreads();
        }
        if (t == 0) logits[e] = red[0];
        __syncthreads();
    }

    if (t == 0) {
        float mx = logits[0];
#pragma unroll
        for (int e = 1; e < NEXP; e++) mx = fmaxf(mx, logits[e]);
        float p[NEXP];
        float s = 0.0f;
#pragma unroll
        for (int e = 0; e < NEXP; e++) { p[e] = expf(logits[e] - mx); s += p[e]; }
        float inv = 1.0f / s;
#pragma unroll
        for (int e = 0; e < NEXP; e++) {
            p[e] *= inv;
            atomicAdd(&g_psum[e], p[e]);
        }
        int i0 = 0;
#pragma unroll
        for (int e = 1; e < NEXP; e++) if (p[e] > p[i0]) i0 = e;
        int i1 = (i0 == 0) ? 1 : 0;
#pragma unroll
        for (int e = 0; e < NEXP; e++) {
            if (e == i0) continue;
            if (p[e] > p[i1]) i1 = e;
        }
        float ssum = p[i0] + p[i1];
        float pn0 = p[i0] / (ssum + 1e-8f);
        float pn1 = p[i1] / (ssum + 1e-8f);
        atomicAdd(&g_tpe[i0], pn0);
        atomicAdd(&g_tpe[i1], pn1);
        int pos0 = atomicAdd(&g_cnt[i0], 1);
        g_list[i0 * N_TOK + pos0]  = n * 2 + 0;
        g_listp[i0 * N_TOK + pos0] = pn0;
        int pos1 = atomicAdd(&g_cnt[i1], 1);
        g_list[i1 * N_TOK + pos1]  = n * 2 + 1;
        g_listp[i1 * N_TOK + pos1] = pn1;
    }
}

// ---------------------------------------------------------------------------
__global__ void split_x_kernel(const float* __restrict__ x) {
    size_t i = ((size_t)blockIdx.x * 256 + threadIdx.x) * 4;
    float4 v = *(const float4*)(x + i);
    __align__(8) __half h[4];
    h[0] = __float2half_rn(v.x);
    h[1] = __float2half_rn(v.y);
    h[2] = __float2half_rn(v.z);
    h[3] = __float2half_rn(v.w);
    *(uint2*)(g_x_h + i) = *(const uint2*)h;
}

// ---------------------------------------------------------------------------
// Transpose + convert weights: in [E][R][C] f32 -> out [E][C][R] fp16.
// 64(R) x 32(C) tile, 256 threads. float4 gmem loads, conflict-free smem
// transpose, 16B fp16 stores.
template<int R, int C, bool W2>
__global__ __launch_bounds__(256) void split_w_kernel(const float* __restrict__ w) {
    __shared__ float tile[32][65];   // [c][r], stride 65 -> conflict-free transpose
    const int e  = blockIdx.z;
    const int c0 = blockIdx.x * 32, r0 = blockIdx.y * 64;
    const int t  = threadIdx.x;

    const int lr  = t >> 2;          // 0..63
    const int lcq = (t & 3) * 8;     // 0,8,16,24
    const float* src = w + ((size_t)e * R + (size_t)(r0 + lr)) * C + c0 + lcq;
    float4 v0 = *(const float4*)src;
    float4 v1 = *(const float4*)(src + 4);
    tile[lcq + 0][lr] = v0.x; tile[lcq + 1][lr] = v0.y;
    tile[lcq + 2][lr] = v0.z; tile[lcq + 3][lr] = v0.w;
    tile[lcq + 4][lr] = v1.x; tile[lcq + 5][lr] = v1.y;
    tile[lcq + 6][lr] = v1.z; tile[lcq + 7][lr] = v1.w;
    __syncthreads();

    const int lc  = t >> 3;          // 0..31
    const int lrq = (t & 7) * 8;     // 0..56
    __align__(16) __half h[8];
#pragma unroll
    for (int i = 0; i < 8; i++) h[i] = __float2half_rn(tile[lc][lrq + i]);
    __half* o = W2 ? g_w2t : g_w1t;
    const size_t ob = ((size_t)e * C + (size_t)(c0 + lc)) * R + r0 + lrq;
    *(uint4*)(o + ob) = *(const uint4*)h;
}

// ---------------------------------------------------------------------------
// Grouped GEMM via warp-level fp16 HMMA, single pass (fp32 accumulate).
// CTA tile M=128 x N=128, K chunk = 64, 3-stage cp.async pipeline.
// 8 warps: warp_m = wid&1 (64 rows), warp_n = wid>>1 (32 cols).
// Stage: A(16K) | B(16K) = 32K, SW128 swizzle. 2 CTAs/SM.
#define OFF_ROWS  64u
#define OFF_PROBS 576u
#define OFF_BUF   2048u
#define B_OFF     16384u
#define STAGE_SZ  32768u
#define SMEM_BYTES (OFF_BUF + 3 * STAGE_SZ)

static __device__ __forceinline__ void prefetch_chunk(
    uint32_t sbuf, int k0,
    const __half* pa, const __half* pb, const uint32_t* dst) {
#pragma unroll
    for (int j = 0; j < 4; j++) cp16(sbuf +         dst[j], pa + k0 + j * 8);
#pragma unroll
    for (int j = 0; j < 4; j++) cp16(sbuf + B_OFF + dst[j], pb + k0 + j * 8);
}

template<int KTOT, int NG, bool PHASE2>
__global__ __launch_bounds__(256, 2) void moe_gemm(const float* __restrict__ bias,
                                                   float* __restrict__ out) {
    constexpr int NCHUNK = KTOT / 64;
    extern __shared__ char smem[];

    const int e = blockIdx.z;
    const int count = g_cnt[e];
    const int m0 = blockIdx.y * 128;
    if (m0 >= count) return;
    const int n0 = blockIdx.x * 128;
    const int tid = threadIdx.x;
    const int wid = tid >> 5, lane = tid & 31;
    const int warp_m = wid & 1;       // 0..1 -> 64-row block
    const int warp_n = wid >> 1;      // 0..3 -> 32-col block
    const uint32_t sbase = smem_u32(smem);

    int*   rows_s  = (int*)(smem + OFF_ROWS);
    float* probs_s = (float*)(smem + OFF_PROBS);
    if (tid < 128) {
        int m = m0 + tid;
        int idx = e * N_TOK + (m < count ? m : count - 1);
        rows_s[tid]  = g_list[idx];
        probs_s[tid] = g_listp[idx];
    }
    __syncthreads();

    // ---- gather/load geometry (identical to store-side swizzle) ----
    const int arow = tid >> 1;
    const int coff = (tid & 1) * 32;
    const int packed = rows_s[arow];
    size_t abase;
    if (PHASE2) abase = ((size_t)(packed & 1) * N_TOK + (size_t)(packed >> 1)) * (size_t)KTOT;
    else        abase = (size_t)(packed >> 1) * (size_t)KTOT;
    const __half* Asrc = PHASE2 ? g_h : g_x_h;
    const __half* Bsrc = PHASE2 ? g_w2t : g_w1t;
    const __half* pa = Asrc + abase + coff;
    const __half* pb = Bsrc + ((size_t)e * NG + (size_t)(n0 + arow)) * (size_t)KTOT + coff;

    uint32_t dst[4];
#pragma unroll
    for (int j = 0; j < 4; j++) {
        int c16 = (tid & 1) * 4 + j;
        dst[j] = (uint32_t)(arow * 128 + ((c16 ^ (arow & 7)) * 16));
    }

    // ---- ldmatrix address components ----
    const int a_r  = lane & 15;
    const int a_kb = lane >> 4;
    const int b_r  = (lane & 7) + ((lane >> 4) << 3);
    const int b_kb = (lane >> 3) & 1;

    float acc[4][4][4];
#pragma unroll
    for (int i = 0; i < 4; i++)
#pragma unroll
        for (int j = 0; j < 4; j++)
#pragma unroll
            for (int q = 0; q < 4; q++) acc[i][j][q] = 0.0f;

    // Prologue: prefetch chunks 0,1
    prefetch_chunk(sbase + OFF_BUF + 0 * STAGE_SZ, 0,  pa, pb, dst);
    CP_COMMIT();
    prefetch_chunk(sbase + OFF_BUF + 1 * STAGE_SZ, 64, pa, pb, dst);
    CP_COMMIT();

    for (int c = 0; c < NCHUNK; c++) {
        if (c + 2 < NCHUNK)
            prefetch_chunk(sbase + OFF_BUF + (uint32_t)((c + 2) % 3) * STAGE_SZ, (c + 2) * 64,
                           pa, pb, dst);
        CP_COMMIT();
        CP_WAIT2();
        __syncthreads();

        const uint32_t sA = sbase + OFF_BUF + (uint32_t)(c % 3) * STAGE_SZ;
        const uint32_t sB = sA + B_OFF;

#pragma unroll
        for (int ks = 0; ks < 4; ks++) {
            uint32_t ah[4][4], bh[4][2];
#pragma unroll
            for (int mf = 0; mf < 4; mf++) {
                int row = warp_m * 64 + mf * 16 + a_r;
                uint32_t off = (uint32_t)(row * 128 + (((2 * ks + a_kb) ^ (row & 7)) << 4));
                ldsm4(ah[mf][0], ah[mf][1], ah[mf][2], ah[mf][3], sA + off);
            }
#pragma unroll
            for (int np = 0; np < 2; np++) {
                int row = warp_n * 32 + np * 16 + b_r;
                uint32_t off = (uint32_t)(row * 128 + (((2 * ks + b_kb) ^ (row & 7)) << 4));
                ldsm4(bh[2 * np][0], bh[2 * np][1], bh[2 * np + 1][0], bh[2 * np + 1][1], sB + off);
            }
#pragma unroll
            for (int mf = 0; mf < 4; mf++)
#pragma unroll
                for (int nf = 0; nf < 4; nf++) mma16816(acc[mf][nf], ah[mf], bh[nf]);
        }
        __syncthreads();
    }

    // ---- epilogue ----
#pragma unroll
    for (int mf = 0; mf < 4; mf++) {
#pragma unroll
        for (int rr = 0; rr < 2; rr++) {
            const int row = warp_m * 64 + mf * 16 + (lane >> 2) + rr * 8;   // 0..127
            const int m = m0 + row;
            if (m >= count) continue;
            const int pk = rows_s[row];
            if (!PHASE2) {
                const int tok = pk >> 1, slot = pk & 1;
                const size_t hb = ((size_t)slot * N_TOK + (size_t)tok) * FDIM;
#pragma unroll
                for (int nf = 0; nf < 4; nf++) {
#pragma unroll
                    for (int jj = 0; jj < 2; jj++) {
                        const int col = n0 + warp_n * 32 + nf * 8 + 2 * (lane & 3) + jj;
                        float h = acc[mf][nf][rr * 2 + jj] + bias[(size_t)e * NG + col];
                        h = 0.5f * h * (1.0f + erff(h * 0.70710678118654752f));
                        g_h[hb + col] = __float2half_rn(h);
                    }
                }
            } else {
                const int tok = pk >> 1;
                const float prob = probs_s[row];
                float* orow = out + (size_t)tok * DIM;
#pragma unroll
                for (int nf = 0; nf < 4; nf++) {
#pragma unroll
                    for (int jj = 0; jj < 2; jj++) {
                        const int col = n0 + warp_n * 32 + nf * 8 + 2 * (lane & 3) + jj;
                        float v = (acc[mf][nf][rr * 2 + jj] + bias[(size_t)e * NG + col]) * prob;
                        atomicAdd(orow + col, v);
                    }
                }
            }
        }
    }
}

// ---------------------------------------------------------------------------
__global__ void finalize_kernel(float* __restrict__ out, int out_size) {
    if (out_size <= N_TOK * DIM) return;
    float s = 0.0f;
#pragma unroll
    for (int e = 0; e < NEXP; e++) s += g_tpe[e];
    float loss = 0.0f;
#pragma unroll
    for (int e = 0; e < NEXP; e++)
        loss += g_tpe[e] / (s + 1e-8f) * (g_psum[e] / (float)N_TOK);
    loss *= (float)NEXP;
    out[N_TOK * DIM] = loss;
}

// ---------------------------------------------------------------------------
extern "C" void kernel_launch(void* const* d_in, const int* in_sizes, int n_in,
                              void* d_out, int out_size) {
    const float* x   = (const float*)d_in[0];
    const float* gw  = (const float*)d_in[1];
    const float* w1  = (const float*)d_in[2];
    const float* b1  = (const float*)d_in[3];
    const float* w2  = (const float*)d_in[4];
    const float* b2  = (const float*)d_in[5];
    float* out = (float*)d_out;

    cudaFuncSetAttribute(moe_gemm<DIM, FDIM, false>,
                         cudaFuncAttributeMaxDynamicSharedMemorySize, SMEM_BYTES);
    cudaFuncSetAttribute(moe_gemm<FDIM, DIM, true>,
                         cudaFuncAttributeMaxDynamicSharedMemorySize, SMEM_BYTES);

    zero_kernel<<<((out_size >> 2) + 255) / 256, 256>>>(out, out_size);
    gate_kernel<<<N_TOK, 128>>>(x, gw);
    split_x_kernel<<<(N_TOK * DIM) / 1024, 256>>>(x);
    split_w_kernel<DIM, FDIM, false><<<dim3(FDIM / 32, DIM / 64, NEXP), 256>>>(w1);
    split_w_kernel<FDIM, DIM, true><<<dim3(DIM / 32, FDIM / 64, NEXP), 256>>>(w2);
    moe_gemm<DIM, FDIM, false><<<dim3(FDIM / 128, N_TOK / 128, NEXP), 256, SMEM_BYTES>>>(b1, out);
    moe_gemm<FDIM, DIM, true><<<dim3(DIM / 128, N_TOK / 128, NEXP), 256, SMEM_BYTES>>>(b2, out);
    finalize_kernel<<<1, 1>>>(out, out_size);
}

// round 11
// speedup vs baseline: 2.4905x; 1.0028x over previous
#include <cuda_runtime.h>
#include <cuda_fp16.h>
#include <math.h>
#include <stdint.h>

#define N_TOK 4096
#define DIM   1024
#define FDIM  4096
#define NEXP  8

// ---------------------------------------------------------------------------
// Scratch (static device globals; no runtime allocation)
__device__ __half g_x_h[(size_t)N_TOK * DIM];
__device__ __half g_w1t[(size_t)NEXP * FDIM * DIM];   // [e][f][d]
__device__ __half g_w2t[(size_t)NEXP * DIM * FDIM];   // [e][d][f]
__device__ __half g_h[(size_t)2 * N_TOK * FDIM];      // [slot*N_TOK+tok][f]
__device__ int   g_list[NEXP * N_TOK];
__device__ float g_listp[NEXP * N_TOK];
__device__ int   g_cnt[NEXP];
__device__ float g_tpe[NEXP];
__device__ float g_psum[NEXP];

// ---------------------------------------------------------------------------
// PTX helpers (sm_80-era only: cp.async, ldmatrix, mma.sync — valid on sm_100)
static __device__ __forceinline__ uint32_t smem_u32(const void* p) {
    uint32_t a;
    asm("{ .reg .u64 t; cvta.to.shared.u64 t, %1; cvt.u32.u64 %0, t; }" : "=r"(a) : "l"(p));
    return a;
}
static __device__ __forceinline__ void cp16(uint32_t dst, const void* src) {
    asm volatile("cp.async.cg.shared.global [%0], [%1], 16;" :: "r"(dst), "l"(src));
}
#define CP_COMMIT()  asm volatile("cp.async.commit_group;" ::: "memory")
#define CP_WAIT2()   asm volatile("cp.async.wait_group 2;" ::: "memory")

static __device__ __forceinline__ void ldsm4(uint32_t& r0, uint32_t& r1, uint32_t& r2,
                                             uint32_t& r3, uint32_t addr) {
    asm volatile("ldmatrix.sync.aligned.m8n8.x4.shared.b16 {%0,%1,%2,%3}, [%4];"
                 : "=r"(r0), "=r"(r1), "=r"(r2), "=r"(r3) : "r"(addr));
}
static __device__ __forceinline__ void mma16816(float* c, const uint32_t* a, const uint32_t* b) {
    asm volatile(
        "mma.sync.aligned.m16n8k16.row.col.f32.f16.f16.f32 "
        "{%0,%1,%2,%3}, {%4,%5,%6,%7}, {%8,%9}, {%0,%1,%2,%3};"
        : "+f"(c[0]), "+f"(c[1]), "+f"(c[2]), "+f"(c[3])
        : "r"(a[0]), "r"(a[1]), "r"(a[2]), "r"(a[3]), "r"(b[0]), "r"(b[1]));
}

// ---------------------------------------------------------------------------
__global__ void zero_kernel(float* __restrict__ out, int out_size) {
    const int n4 = out_size >> 2;
    int i = blockIdx.x * blockDim.x + threadIdx.x;
    if (i < n4) *(float4*)(out + 4 * (size_t)i) = make_float4(0.f, 0.f, 0.f, 0.f);
    if (blockIdx.x == 0 && threadIdx.x == 0) {
        for (int r = n4 * 4; r < out_size; r++) out[r] = 0.0f;
    }
    if (blockIdx.x == 0 && threadIdx.x < NEXP) {
        g_cnt[threadIdx.x]  = 0;
        g_tpe[threadIdx.x]  = 0.0f;
        g_psum[threadIdx.x] = 0.0f;
    }
}

// ---------------------------------------------------------------------------
__global__ __launch_bounds__(128) void gate_kernel(const float* __restrict__ x,
                                                   const float* __restrict__ gw) {
    const int n = blockIdx.x;
    const int t = threadIdx.x;
    float acc[NEXP];
#pragma unroll
    for (int e = 0; e < NEXP; e++) acc[e] = 0.0f;

    const float* xr = x + (size_t)n * DIM;
    for (int i = t; i < DIM; i += 128) {
        float xv = xr[i];
        const float* g = gw + (size_t)i * NEXP;
#pragma unroll
        for (int e = 0; e < NEXP; e++) acc[e] += xv * g[e];
    }

    __shared__ float red[128];
    __shared__ float logits[NEXP];
    for (int e = 0; e < NEXP; e++) {
        red[t] = acc[e];
        __syncthreads();
        for (int s = 64; s > 0; s >>= 1) {
            if (t < s) red[t] += red[t + s];
            __syncthreads();
        }
        if (t == 0) logits[e] = red[0];
        __syncthreads();
    }

    if (t == 0) {
        float mx = logits[0];
#pragma unroll
        for (int e = 1; e < NEXP; e++) mx = fmaxf(mx, logits[e]);
        float p[NEXP];
        float s = 0.0f;
#pragma unroll
        for (int e = 0; e < NEXP; e++) { p[e] = expf(logits[e] - mx); s += p[e]; }
        float inv = 1.0f / s;
#pragma unroll
        for (int e = 0; e < NEXP; e++) {
            p[e] *= inv;
            atomicAdd(&g_psum[e], p[e]);
        }
        int i0 = 0;
#pragma unroll
        for (int e = 1; e < NEXP; e++) if (p[e] > p[i0]) i0 = e;
        int i1 = (i0 == 0) ? 1 : 0;
#pragma unroll
        for (int e = 0; e < NEXP; e++) {
            if (e == i0) continue;
            if (p[e] > p[i1]) i1 = e;
        }
        float ssum = p[i0] + p[i1];
        float pn0 = p[i0] / (ssum + 1e-8f);
        float pn1 = p[i1] / (ssum + 1e-8f);
        atomicAdd(&g_tpe[i0], pn0);
        atomicAdd(&g_tpe[i1], pn1);
        int pos0 = atomicAdd(&g_cnt[i0], 1);
        g_list[i0 * N_TOK + pos0]  = n * 2 + 0;
        g_listp[i0 * N_TOK + pos0] = pn0;
        int pos1 = atomicAdd(&g_cnt[i1], 1);
        g_list[i1 * N_TOK + pos1]  = n * 2 + 1;
        g_listp[i1 * N_TOK + pos1] = pn1;
    }
}

// ---------------------------------------------------------------------------
__global__ void split_x_kernel(const float* __restrict__ x) {
    size_t i = ((size_t)blockIdx.x * 256 + threadIdx.x) * 4;
    float4 v = *(const float4*)(x + i);
    __align__(8) __half h[4];
    h[0] = __float2half_rn(v.x);
    h[1] = __float2half_rn(v.y);
    h[2] = __float2half_rn(v.z);
    h[3] = __float2half_rn(v.w);
    *(uint2*)(g_x_h + i) = *(const uint2*)h;
}

// ---------------------------------------------------------------------------
// Transpose + convert weights: in [E][R][C] f32 -> out [E][C][R] fp16.
// 64(R) x 32(C) tile, 256 threads. float4 gmem loads, conflict-free smem
// transpose, 16B fp16 stores.
template<int R, int C, bool W2>
__global__ __launch_bounds__(256) void split_w_kernel(const float* __restrict__ w) {
    __shared__ float tile[32][65];   // [c][r], stride 65 -> conflict-free transpose
    const int e  = blockIdx.z;
    const int c0 = blockIdx.x * 32, r0 = blockIdx.y * 64;
    const int t  = threadIdx.x;

    const int lr  = t >> 2;          // 0..63
    const int lcq = (t & 3) * 8;     // 0,8,16,24
    const float* src = w + ((size_t)e * R + (size_t)(r0 + lr)) * C + c0 + lcq;
    float4 v0 = *(const float4*)src;
    float4 v1 = *(const float4*)(src + 4);
    tile[lcq + 0][lr] = v0.x; tile[lcq + 1][lr] = v0.y;
    tile[lcq + 2][lr] = v0.z; tile[lcq + 3][lr] = v0.w;
    tile[lcq + 4][lr] = v1.x; tile[lcq + 5][lr] = v1.y;
    tile[lcq + 6][lr] = v1.z; tile[lcq + 7][lr] = v1.w;
    __syncthreads();

    const int lc  = t >> 3;          // 0..31
    const int lrq = (t & 7) * 8;     // 0..56
    __align__(16) __half h[8];
#pragma unroll
    for (int i = 0; i < 8; i++) h[i] = __float2half_rn(tile[lc][lrq + i]);
    __half* o = W2 ? g_w2t : g_w1t;
    const size_t ob = ((size_t)e * C + (size_t)(c0 + lc)) * R + r0 + lrq;
    *(uint4*)(o + ob) = *(const uint4*)h;
}

// ---------------------------------------------------------------------------
// Grouped GEMM via warp-level fp16 HMMA, single pass (fp32 accumulate).
// CTA tile M=128 x N=128, K chunk = 64, 3-stage cp.async pipeline.
// 8 warps: warp_m = wid&1 (64 rows), warp_n = wid>>1 (32 cols).
// Stage: A(16K) | B(16K) = 32K, SW128 swizzle. 2 CTAs/SM.
#define OFF_ROWS  64u
#define OFF_PROBS 576u
#define OFF_BUF   2048u
#define B_OFF     16384u
#define STAGE_SZ  32768u
#define SMEM_BYTES (OFF_BUF + 3 * STAGE_SZ)

static __device__ __forceinline__ void prefetch_chunk(
    uint32_t sbuf, int k0,
    const __half* pa, const __half* pb, const uint32_t* dst) {
#pragma unroll
    for (int j = 0; j < 4; j++) cp16(sbuf +         dst[j], pa + k0 + j * 8);
#pragma unroll
    for (int j = 0; j < 4; j++) cp16(sbuf + B_OFF + dst[j], pb + k0 + j * 8);
}

template<int KTOT, int NG, bool PHASE2>
__global__ __launch_bounds__(256, 2) void moe_gemm(const float* __restrict__ bias,
                                                   float* __restrict__ out) {
    constexpr int NCHUNK = KTOT / 64;
    extern __shared__ char smem[];

    const int e = blockIdx.z;
    const int count = g_cnt[e];
    const int m0 = blockIdx.y * 128;
    if (m0 >= count) return;
    const int n0 = blockIdx.x * 128;
    const int tid = threadIdx.x;
    const int wid = tid >> 5, lane = tid & 31;
    const int warp_m = wid & 1;       // 0..1 -> 64-row block
    const int warp_n = wid >> 1;      // 0..3 -> 32-col block
    const uint32_t sbase = smem_u32(smem);

    int*   rows_s  = (int*)(smem + OFF_ROWS);
    float* probs_s = (float*)(smem + OFF_PROBS);
    if (tid < 128) {
        int m = m0 + tid;
        int idx = e * N_TOK + (m < count ? m : count - 1);
        rows_s[tid]  = g_list[idx];
        probs_s[tid] = g_listp[idx];
    }
    __syncthreads();

    // ---- gather/load geometry (identical to store-side swizzle) ----
    const int arow = tid >> 1;
    const int coff = (tid & 1) * 32;
    const int packed = rows_s[arow];
    size_t abase;
    if (PHASE2) abase = ((size_t)(packed & 1) * N_TOK + (size_t)(packed >> 1)) * (size_t)KTOT;
    else        abase = (size_t)(packed >> 1) * (size_t)KTOT;
    const __half* Asrc = PHASE2 ? g_h : g_x_h;
    const __half* Bsrc = PHASE2 ? g_w2t : g_w1t;
    const __half* pa = Asrc + abase + coff;
    const __half* pb = Bsrc + ((size_t)e * NG + (size_t)(n0 + arow)) * (size_t)KTOT + coff;

    uint32_t dst[4];
#pragma unroll
    for (int j = 0; j < 4; j++) {
        int c16 = (tid & 1) * 4 + j;
        dst[j] = (uint32_t)(arow * 128 + ((c16 ^ (arow & 7)) * 16));
    }

    // ---- ldmatrix address components ----
    const int a_r  = lane & 15;
    const int a_kb = lane >> 4;
    const int b_r  = (lane & 7) + ((lane >> 4) << 3);
    const int b_kb = (lane >> 3) & 1;

    float acc[4][4][4];
#pragma unroll
    for (int i = 0; i < 4; i++)
#pragma unroll
        for (int j = 0; j < 4; j++)
#pragma unroll
            for (int q = 0; q < 4; q++) acc[i][j][q] = 0.0f;

    // Prologue: prefetch chunks 0,1
    prefetch_chunk(sbase + OFF_BUF + 0 * STAGE_SZ, 0,  pa, pb, dst);
    CP_COMMIT();
    prefetch_chunk(sbase + OFF_BUF + 1 * STAGE_SZ, 64, pa, pb, dst);
    CP_COMMIT();

    for (int c = 0; c < NCHUNK; c++) {
        if (c + 2 < NCHUNK)
            prefetch_chunk(sbase + OFF_BUF + (uint32_t)((c + 2) % 3) * STAGE_SZ, (c + 2) * 64,
                           pa, pb, dst);
        CP_COMMIT();
        CP_WAIT2();
        __syncthreads();

        const uint32_t sA = sbase + OFF_BUF + (uint32_t)(c % 3) * STAGE_SZ;
        const uint32_t sB = sA + B_OFF;

#pragma unroll
        for (int ks = 0; ks < 4; ks++) {
            uint32_t ah[4][4], bh[4][2];
#pragma unroll
            for (int mf = 0; mf < 4; mf++) {
                int row = warp_m * 64 + mf * 16 + a_r;
                uint32_t off = (uint32_t)(row * 128 + (((2 * ks + a_kb) ^ (row & 7)) << 4));
                ldsm4(ah[mf][0], ah[mf][1], ah[mf][2], ah[mf][3], sA + off);
            }
#pragma unroll
            for (int np = 0; np < 2; np++) {
                int row = warp_n * 32 + np * 16 + b_r;
                uint32_t off = (uint32_t)(row * 128 + (((2 * ks + b_kb) ^ (row & 7)) << 4));
                ldsm4(bh[2 * np][0], bh[2 * np][1], bh[2 * np + 1][0], bh[2 * np + 1][1], sB + off);
            }
#pragma unroll
            for (int mf = 0; mf < 4; mf++)
#pragma unroll
                for (int nf = 0; nf < 4; nf++) mma16816(acc[mf][nf], ah[mf], bh[nf]);
        }
        __syncthreads();
    }

    // ---- epilogue ----
#pragma unroll
    for (int mf = 0; mf < 4; mf++) {
#pragma unroll
        for (int rr = 0; rr < 2; rr++) {
            const int row = warp_m * 64 + mf * 16 + (lane >> 2) + rr * 8;   // 0..127
            const int m = m0 + row;
            if (m >= count) continue;
            const int pk = rows_s[row];
            if (!PHASE2) {
                const int tok = pk >> 1, slot = pk & 1;
                const size_t hb = ((size_t)slot * N_TOK + (size_t)tok) * FDIM;
#pragma unroll
                for (int nf = 0; nf < 4; nf++) {
#pragma unroll
                    for (int jj = 0; jj < 2; jj++) {
                        const int col = n0 + warp_n * 32 + nf * 8 + 2 * (lane & 3) + jj;
                        float h = acc[mf][nf][rr * 2 + jj] + bias[(size_t)e * NG + col];
                        h = 0.5f * h * (1.0f + erff(h * 0.70710678118654752f));
                        g_h[hb + col] = __float2half_rn(h);
                    }
                }
            } else {
                const int tok = pk >> 1;
                const float prob = probs_s[row];
                float* orow = out + (size_t)tok * DIM;
#pragma unroll
                for (int nf = 0; nf < 4; nf++) {
#pragma unroll
                    for (int jj = 0; jj < 2; jj++) {
                        const int col = n0 + warp_n * 32 + nf * 8 + 2 * (lane & 3) + jj;
                        float v = (acc[mf][nf][rr * 2 + jj] + bias[(size_t)e * NG + col]) * prob;
                        atomicAdd(orow + col, v);
                    }
                }
            }
        }
    }
}

// ---------------------------------------------------------------------------
__global__ void finalize_kernel(float* __restrict__ out, int out_size) {
    if (out_size <= N_TOK * DIM) return;
    float s = 0.0f;
#pragma unroll
    for (int e = 0; e < NEXP; e++) s += g_tpe[e];
    float loss = 0.0f;
#pragma unroll
    for (int e = 0; e < NEXP; e++)
        loss += g_tpe[e] / (s + 1e-8f) * (g_psum[e] / (float)N_TOK);
    loss *= (float)NEXP;
    out[N_TOK * DIM] = loss;
}

// ---------------------------------------------------------------------------
extern "C" void kernel_launch(void* const* d_in, const int* in_sizes, int n_in,
                              void* d_out, int out_size) {
    const float* x   = (const float*)d_in[0];
    const float* gw  = (const float*)d_in[1];
    const float* w1  = (const float*)d_in[2];
    const float* b1  = (const float*)d_in[3];
    const float* w2  = (const float*)d_in[4];
    const float* b2  = (const float*)d_in[5];
    float* out = (float*)d_out;

    cudaFuncSetAttribute(moe_gemm<DIM, FDIM, false>,
                         cudaFuncAttributeMaxDynamicSharedMemorySize, SMEM_BYTES);
    cudaFuncSetAttribute(moe_gemm<FDIM, DIM, true>,
                         cudaFuncAttributeMaxDynamicSharedMemorySize, SMEM_BYTES);

    zero_kernel<<<((out_size >> 2) + 255) / 256, 256>>>(out, out_size);
    gate_kernel<<<N_TOK, 128>>>(x, gw);
    split_x_kernel<<<(N_TOK * DIM) / 1024, 256>>>(x);
    split_w_kernel<DIM, FDIM, false><<<dim3(FDIM / 32, DIM / 64, NEXP), 256>>>(w1);
    split_w_kernel<FDIM, DIM, true><<<dim3(DIM / 32, FDIM / 64, NEXP), 256>>>(w2);
    moe_gemm<DIM, FDIM, false><<<dim3(FDIM / 128, N_TOK / 128, NEXP), 256, SMEM_BYTES>>>(b1, out);
    moe_gemm<FDIM, DIM, true><<<dim3(DIM / 128, N_TOK / 128, NEXP), 256, SMEM_BYTES>>>(b2, out);
    finalize_kernel<<<1, 1>>>(out, out_size);
}